// round 2
// baseline (speedup 1.0000x reference)
#include <cuda_runtime.h>
#include <math.h>

#define B_   32
#define T_   1000
#define F_   80
#define H_   1024
#define HH_  2048
#define MT_  32000
#define NBLK 128
#define EPSV 1e-5f

// ---------------- scratch (static device globals; no allocation) ----------------
__device__ float g_w[65536000];          // [32000][2048] projected+raw w (reused by both layers)
__device__ float g_hs1[32768000];        // [32000][1024] layer-1 hidden sequence
__device__ float g_hT[H_ * B_];          // transposed h: [k=1024][i=32]
__device__ float g_colsum[HH_];
__device__ float g_colsq[HH_];
__device__ float g_scale[HH_];
__device__ float g_shift[HH_];
__device__ float g_psum[B_ * NBLK];      // per-row, per-block LN partial sums [i][block]
__device__ float g_psq[B_ * NBLK];
__device__ unsigned g_bar_cnt = 0;
__device__ unsigned g_bar_gen = 0;

// ---------------- grid-wide barrier (generation counter, self-resetting) ----------------
__device__ __forceinline__ void gridbar() {
    __syncthreads();
    if (threadIdx.x == 0) {
        volatile unsigned* genp = &g_bar_gen;
        unsigned gen = *genp;
        __threadfence();
        unsigned arr = atomicAdd(&g_bar_cnt, 1u);
        if (arr == NBLK - 1) {
            g_bar_cnt = 0;
            __threadfence();
            atomicAdd(&g_bar_gen, 1u);
        } else {
            while (*genp == gen) { }
            __threadfence();
        }
    }
    __syncthreads();
}

// ---------------- SGEMM (NT): C[m][n] = sum_k A[m][k]*B[n][k], N fixed = 2048 ----------------
__global__ void __launch_bounds__(256)
sgemm_nt(const float* __restrict__ A, const float* __restrict__ Bm,
         float* __restrict__ C, int K)
{
    __shared__ float As[8][128];
    __shared__ float Bs[8][128];
    const int tid  = threadIdx.x;
    const int m0   = blockIdx.y * 128;
    const int n0   = blockIdx.x * 128;
    const int lrow = tid >> 1;
    const int lk4  = (tid & 1) * 4;
    const int tx   = tid & 15, ty = tid >> 4;
    const float* Ap = A  + (size_t)(m0 + lrow) * K + lk4;
    const float* Bp = Bm + (size_t)(n0 + lrow) * K + lk4;
    float acc[8][8];
    #pragma unroll
    for (int i = 0; i < 8; i++)
        #pragma unroll
        for (int j = 0; j < 8; j++) acc[i][j] = 0.0f;

    for (int k0 = 0; k0 < K; k0 += 8) {
        float4 av = *(const float4*)(Ap + k0);
        float4 bv = *(const float4*)(Bp + k0);
        __syncthreads();
        As[lk4 + 0][lrow] = av.x; As[lk4 + 1][lrow] = av.y;
        As[lk4 + 2][lrow] = av.z; As[lk4 + 3][lrow] = av.w;
        Bs[lk4 + 0][lrow] = bv.x; Bs[lk4 + 1][lrow] = bv.y;
        Bs[lk4 + 2][lrow] = bv.z; Bs[lk4 + 3][lrow] = bv.w;
        __syncthreads();
        #pragma unroll
        for (int kk = 0; kk < 8; kk++) {
            float a[8], bb[8];
            *(float4*)&a[0]  = *(const float4*)&As[kk][ty * 8];
            *(float4*)&a[4]  = *(const float4*)&As[kk][ty * 8 + 4];
            *(float4*)&bb[0] = *(const float4*)&Bs[kk][tx * 8];
            *(float4*)&bb[4] = *(const float4*)&Bs[kk][tx * 8 + 4];
            #pragma unroll
            for (int i = 0; i < 8; i++)
                #pragma unroll
                for (int j = 0; j < 8; j++)
                    acc[i][j] += a[i] * bb[j];
        }
    }
    #pragma unroll
    for (int i = 0; i < 8; i++) {
        float* Cp = C + (size_t)(m0 + ty * 8 + i) * HH_ + n0 + tx * 8;
        *(float4*)Cp       = make_float4(acc[i][0], acc[i][1], acc[i][2], acc[i][3]);
        *(float4*)(Cp + 4) = make_float4(acc[i][4], acc[i][5], acc[i][6], acc[i][7]);
    }
}

// ---------------- BatchNorm column stats over 32000 rows ----------------
__global__ void __launch_bounds__(256)
bn_stats(const float* __restrict__ w)
{
    int col = blockIdx.x * 256 + threadIdx.x;            // grid.x = 8
    size_t r0 = (size_t)blockIdx.y * 1000;               // grid.y = 32
    float s = 0.0f, q = 0.0f;
    const float* p = w + r0 * HH_ + col;
    #pragma unroll 4
    for (int r = 0; r < 1000; r++) {
        float v = p[(size_t)r * HH_];
        s += v; q += v * v;
    }
    atomicAdd(&g_colsum[col], s);
    atomicAdd(&g_colsq[col], q);
}

__global__ void __launch_bounds__(256)
bn_finalize(const float* __restrict__ gamma, const float* __restrict__ beta)
{
    int c = blockIdx.x * 256 + threadIdx.x;              // grid 8
    float mean = g_colsum[c] * (1.0f / 32000.0f);
    float var  = g_colsq[c] * (1.0f / 32000.0f) - mean * mean;
    float sc = gamma[c] * rsqrtf(var + EPSV);
    g_scale[c] = sc;
    g_shift[c] = beta[c] - mean * sc;
}

// ---------------- Persistent LiGRU recurrence ----------------
// 128 blocks x 256 threads. Block b owns h-cols [b*8, b*8+8) and the paired
// gate columns {cb+jj, 1024+cb+jj}. U slice lives in SMEM (transposed).
// SMEM layout (floats):
//   UsT   [1024][16]  @ 0       (65536 B)
//   red   [8][512]    @ 16384   (16384 B)
//   uhbuf [512]       @ 20480
//   ssum  [32*8]      @ 20992
//   ssq   [32*8]      @ 21248
//   smean [32]        @ 21504
//   srstd [32]        @ 21536
//   scs   [16]        @ 21568
//   shs   [16]        @ 21584   -> total 21600 floats = 86400 bytes
#define REC_SMEM_FLOATS 21600

__global__ void __launch_bounds__(256, 1)
rec_kernel(const float* __restrict__ w, const float* __restrict__ U,
           float* __restrict__ hs_out)
{
    extern __shared__ float sm[];
    float* UsT   = sm;
    float* red   = sm + 16384;
    float* uhbuf = sm + 20480;
    float* ssum  = sm + 20992;
    float* ssq   = sm + 21248;
    float* smean = sm + 21504;
    float* srstd = sm + 21536;
    float* scs   = sm + 21568;
    float* shs   = sm + 21584;

    const int tid = threadIdx.x;
    const int b   = blockIdx.x;
    const int cb  = b * 8;

    // One-time: load U slice transposed (UsT[k][jj]) and fold BN scale/shift
    for (int idx = tid; idx < 16 * 1024; idx += 256) {
        int jj = idx >> 10, k = idx & 1023;
        int urow = (jj < 8) ? (cb + jj) : (H_ + cb + jj - 8);
        UsT[k * 16 + jj] = U[(size_t)urow * H_ + k];
    }
    if (tid < 16) {
        int col = (tid < 8) ? (cb + tid) : (H_ + cb + tid - 8);
        scs[tid] = g_scale[col];
        shs[tid] = g_shift[col];
    }
    __syncthreads();

    const int warp  = tid >> 5, lane = tid & 31;
    const int i0    = (lane & 7) * 4;    // 4 batch rows
    const int jj0   = (lane >> 3) * 4;   // 4 gate cols
    const int kbase = warp * 128;        // warp's K segment

    const int ui = tid >> 3;             // batch row for update/stats (0..31)
    const int uj = tid & 7;              // h-col within block / stats part

    float hreg = 0.0f;                   // this thread's own h[ui][cb+uj]

    for (int t = 0; t < T_; ++t) {
        // -- per-warp partial GEMM over K segment --
        float acc[4][4];
        #pragma unroll
        for (int a = 0; a < 4; a++) {
            acc[a][0] = 0.f; acc[a][1] = 0.f; acc[a][2] = 0.f; acc[a][3] = 0.f;
        }
        const float* hseg = g_hT + kbase * B_ + i0;
        const float* useg = UsT + kbase * 16 + jj0;
        #pragma unroll 4
        for (int ku = 0; ku < 128; ku += 8) {
            float4 hv[8], uv[8];
            #pragma unroll
            for (int u = 0; u < 8; u++)
                hv[u] = __ldcg((const float4*)(hseg + (ku + u) * B_));
            #pragma unroll
            for (int u = 0; u < 8; u++)
                uv[u] = *(const float4*)(useg + (ku + u) * 16);
            #pragma unroll
            for (int u = 0; u < 8; u++) {
                acc[0][0] += hv[u].x * uv[u].x; acc[0][1] += hv[u].x * uv[u].y;
                acc[0][2] += hv[u].x * uv[u].z; acc[0][3] += hv[u].x * uv[u].w;
                acc[1][0] += hv[u].y * uv[u].x; acc[1][1] += hv[u].y * uv[u].y;
                acc[1][2] += hv[u].y * uv[u].z; acc[1][3] += hv[u].y * uv[u].w;
                acc[2][0] += hv[u].z * uv[u].x; acc[2][1] += hv[u].z * uv[u].y;
                acc[2][2] += hv[u].z * uv[u].z; acc[2][3] += hv[u].z * uv[u].w;
                acc[3][0] += hv[u].w * uv[u].x; acc[3][1] += hv[u].w * uv[u].y;
                acc[3][2] += hv[u].w * uv[u].z; acc[3][3] += hv[u].w * uv[u].w;
            }
        }
        #pragma unroll
        for (int ii = 0; ii < 4; ii++) {
            *(float4*)(red + warp * 512 + (i0 + ii) * 16 + jj0) =
                make_float4(acc[ii][0], acc[ii][1], acc[ii][2], acc[ii][3]);
        }
        __syncthreads();

        // -- cross-warp K reduction: uhbuf[i*16+jj] --
        for (int o = tid; o < 512; o += 256) {
            float v = 0.0f;
            #pragma unroll
            for (int wv = 0; wv < 8; wv++) v += red[wv * 512 + o];
            uhbuf[o] = v;
        }
        __syncthreads();

        // -- block-local LN partials --
        {
            float v0 = uhbuf[ui * 16 + uj * 2];
            float v1 = uhbuf[ui * 16 + uj * 2 + 1];
            ssum[ui * 8 + uj] = v0 + v1;
            ssq [ui * 8 + uj] = v0 * v0 + v1 * v1;
        }
        __syncthreads();
        if (tid < 32) {
            float S = 0.f, Q = 0.f;
            #pragma unroll
            for (int p = 0; p < 8; p++) { S += ssum[tid * 8 + p]; Q += ssq[tid * 8 + p]; }
            g_psum[tid * NBLK + b] = S;
            g_psq [tid * NBLK + b] = Q;
        }
        gridbar();   // (A) all blocks' LN partials visible

        // -- global LN stats reduce (128 partials per row) --
        {
            float S = 0.f, Q = 0.f;
            const float* ps = g_psum + ui * NBLK + uj * 16;
            const float* pq = g_psq  + ui * NBLK + uj * 16;
            #pragma unroll
            for (int q = 0; q < 16; q++) { S += __ldcg(ps + q); Q += __ldcg(pq + q); }
            ssum[ui * 8 + uj] = S; ssq[ui * 8 + uj] = Q;
        }
        __syncthreads();
        if (tid < 32) {
            float S = 0.f, Q = 0.f;
            #pragma unroll
            for (int p = 0; p < 8; p++) { S += ssum[tid * 8 + p]; Q += ssq[tid * 8 + p]; }
            float mean = S * (1.0f / 2048.0f);
            float var  = Q * (1.0f / 2048.0f) - mean * mean;
            smean[tid] = mean;
            srstd[tid] = rsqrtf(var + EPSV);
        }
        __syncthreads();

        // -- gate + h update (h carried in register) --
        {
            float m = smean[ui], r = srstd[ui];
            float an = (uhbuf[ui * 16 + uj]     - m) * r;
            float zn = (uhbuf[ui * 16 + 8 + uj] - m) * r;
            size_t wrow = (size_t)(ui * T_ + t) * HH_;
            float wa = w[wrow + cb + uj]      * scs[uj]     + shs[uj];
            float wz = w[wrow + H_ + cb + uj] * scs[8 + uj] + shs[8 + uj];
            float a  = wa + an;
            float zx = wz + zn;
            float z  = 1.0f / (1.0f + __expf(-zx));
            float hnew = z * hreg + (1.0f - z) * fmaxf(a, 0.0f);
            hreg = hnew;
            g_hT[(cb + uj) * B_ + ui] = hnew;
            hs_out[(size_t)(ui * T_ + t) * H_ + cb + uj] = hnew;
        }
        gridbar();   // (B) new h visible before next step's GEMM reads
    }
}

// ---------------- launch ----------------
extern "C" void kernel_launch(void* const* d_in, const int* in_sizes, int n_in,
                              void* d_out, int out_size)
{
    const float* x  = (const float*)d_in[0];
    const float* W1 = (const float*)d_in[1];
    const float* U1 = (const float*)d_in[2];
    const float* g1 = (const float*)d_in[3];
    const float* b1 = (const float*)d_in[4];
    const float* W2 = (const float*)d_in[5];
    const float* U2 = (const float*)d_in[6];
    const float* g2 = (const float*)d_in[7];
    const float* b2 = (const float*)d_in[8];
    float* out = (float*)d_out;

    float *w_buf, *hs1, *csum, *csq, *hT;
    cudaGetSymbolAddress((void**)&w_buf, g_w);
    cudaGetSymbolAddress((void**)&hs1,   g_hs1);
    cudaGetSymbolAddress((void**)&csum,  g_colsum);
    cudaGetSymbolAddress((void**)&csq,   g_colsq);
    cudaGetSymbolAddress((void**)&hT,    g_hT);

    cudaFuncSetAttribute(rec_kernel, cudaFuncAttributeMaxDynamicSharedMemorySize,
                         REC_SMEM_FLOATS * 4);

    dim3 gproj(16, 250);

    // ---- Layer 1 ----
    sgemm_nt<<<gproj, 256>>>(x, W1, w_buf, F_);
    cudaMemsetAsync(csum, 0, HH_ * 4);
    cudaMemsetAsync(csq,  0, HH_ * 4);
    bn_stats<<<dim3(8, 32), 256>>>(w_buf);
    bn_finalize<<<8, 256>>>(g1, b1);
    cudaMemsetAsync(hT, 0, H_ * B_ * 4);
    rec_kernel<<<NBLK, 256, REC_SMEM_FLOATS * 4>>>(w_buf, U1, hs1);

    // ---- Layer 2 ----
    sgemm_nt<<<gproj, 256>>>(hs1, W2, w_buf, H_);
    cudaMemsetAsync(csum, 0, HH_ * 4);
    cudaMemsetAsync(csq,  0, HH_ * 4);
    bn_stats<<<dim3(8, 32), 256>>>(w_buf);
    bn_finalize<<<8, 256>>>(g2, b2);
    cudaMemsetAsync(hT, 0, H_ * B_ * 4);
    rec_kernel<<<NBLK, 256, REC_SMEM_FLOATS * 4>>>(w_buf, U2, out);

    (void)in_sizes; (void)n_in; (void)out_size;
}